// round 2
// baseline (speedup 1.0000x reference)
#include <cuda_runtime.h>
#include <math.h>

#define NB 64
#define NT 32
#define NR 49
#define FLOC 1024
#define NQ 512
#define NE 256
#define NH 512
#define NV 10000
#define G4 2048   // 4*HID
#define XD 1024   // [o(512), h(512)]
#define UD 1536   // [a(1024), h(512)]

// ---------------- scratch (device globals; no allocation allowed) ----------
__device__ float g_Wrec[G4 * XD];          // combined [W_ih(:,256:768) | W_hh]
__device__ float g_WattnT[FLOC * NH];      // W_attn transposed [f][h]
__device__ float g_yseq[NT * NB * NE];     // teacher-forced input embeddings
__device__ float g_gatesy[NT * NB * G4];   // y @ W_ihy^T + b_ih + b_hh
__device__ float g_h[NB * NH];
__device__ float g_c[NB * NH];
__device__ float g_x[NB * XD];             // [o, h] GEMM input
__device__ float g_u[NB * UD];             // [a, h] GEMM input
__device__ float g_oall[NT * NB * NH];     // all o_t (vocab GEMM input)
__device__ float g_P[8 * NB * G4];         // k-split partial sums (max shape)

// ---------------- one-time prep: weight repack + embedding gather ----------
__global__ void prep_kernel(const float* __restrict__ W_ih,
                            const float* __restrict__ W_hh,
                            const float* __restrict__ W_attn,
                            const float* __restrict__ emb,
                            const int*   __restrict__ answers)
{
    int stride = gridDim.x * blockDim.x;
    int tid0 = blockIdx.x * blockDim.x + threadIdx.x;
    for (int i = tid0; i < G4 * XD; i += stride) {
        int n = i >> 10, k = i & 1023;
        g_Wrec[i] = (k < NH) ? W_ih[n * 768 + 256 + k] : W_hh[n * NH + (k - NH)];
    }
    for (int i = tid0; i < FLOC * NH; i += stride) {
        int f = i >> 9, h = i & 511;
        g_WattnT[i] = W_attn[h * FLOC + f];
    }
    for (int i = tid0; i < NT * NB * NE; i += stride) {
        int m = i >> 8, e = i & 255;
        int t = m >> 6, b = m & 63;
        int tok = (t == 0) ? 1 : answers[b * NT + (t - 1)];
        g_yseq[i] = emb[tok * NE + e];
    }
}

// ---------------- small-M (M=64) GEMM with k-split partials ----------------
// out_partial[kc][64][N] = X[64, kChunk slice] @ W[N, K]^T  (row-major, K contiguous)
// grid.x = (N/64) * kSplit. Writes to g_P.
__global__ void sg64_kernel(const float* __restrict__ Xp, int ldx_p, int xsel,
                            const float* __restrict__ Wp, int ldw_p, int wsel,
                            int N, int kChunk)
{
    __shared__ float xs[64 * 65];
    __shared__ float ws[64 * 65];
    const float* X; int ldx;
    if (xsel == 0)      { X = Xp;  ldx = ldx_p; }
    else if (xsel == 1) { X = g_x; ldx = XD; }
    else if (xsel == 2) { X = g_h; ldx = NH; }
    else                { X = g_u; ldx = UD; }
    const float* W; int ldw;
    if (wsel == 0)      { W = Wp;       ldw = ldw_p; }
    else if (wsel == 1) { W = g_Wrec;   ldw = XD; }
    else                { W = g_WattnT; ldw = NH; }

    int nTiles = N >> 6;
    int nt = blockIdx.x % nTiles;
    int kc = blockIdx.x / nTiles;
    int n0 = nt << 6;
    int kbase = kc * kChunk;
    int tid = threadIdx.x;
    int tx = tid & 15, ty = tid >> 4;
    float acc[4][4] = {{0.f}};

    for (int kk = 0; kk < kChunk; kk += 64) {
        #pragma unroll
        for (int it = 0; it < 4; it++) {
            int idx = it * 256 + tid;
            int row = idx >> 4;
            int kq = (idx & 15) << 2;
            float4 v = *(const float4*)(X + row * ldx + kbase + kk + kq);
            float* d = &xs[row * 65 + kq];
            d[0] = v.x; d[1] = v.y; d[2] = v.z; d[3] = v.w;
            float4 w = *(const float4*)(W + (n0 + row) * ldw + kbase + kk + kq);
            float* e = &ws[row * 65 + kq];
            e[0] = w.x; e[1] = w.y; e[2] = w.z; e[3] = w.w;
        }
        __syncthreads();
        #pragma unroll 16
        for (int k = 0; k < 64; k++) {
            float xv[4], wv[4];
            #pragma unroll
            for (int i = 0; i < 4; i++) xv[i] = xs[(ty * 4 + i) * 65 + k];
            #pragma unroll
            for (int j = 0; j < 4; j++) wv[j] = ws[(tx + 16 * j) * 65 + k];
            #pragma unroll
            for (int i = 0; i < 4; i++)
                #pragma unroll
                for (int j = 0; j < 4; j++)
                    acc[i][j] = fmaf(xv[i], wv[j], acc[i][j]);
        }
        __syncthreads();
    }
    #pragma unroll
    for (int i = 0; i < 4; i++) {
        int m = ty * 4 + i;
        float* dst = &g_P[(kc * 64 + m) * N + n0];
        #pragma unroll
        for (int j = 0; j < 4; j++)
            dst[tx + 16 * j] = acc[i][j];
    }
}

// ---------------- k-split reduction + state scatter ------------------------
// mode 0: h0 -> g_h, g_x[h-part]
// mode 1: c0 -> g_c
// mode 2: o0 (bias) -> g_x[o-part]
// mode 3: o_t = tanh(.+b_u) -> g_x[o-part], g_oall[t]
__global__ void reduce_kernel(int ksplit, int N, const float* __restrict__ bias,
                              int mode, int t)
{
    int idx = blockIdx.x * blockDim.x + threadIdx.x;
    if (idx >= NB * N) return;
    int b = idx / N, n = idx % N;
    float s = 0.f;
    for (int kc = 0; kc < ksplit; kc++)
        s += g_P[(kc * 64 + b) * N + n];
    if (bias) s += bias[n];
    if (mode == 0)      { g_h[b * NH + n] = s; g_x[b * XD + NH + n] = s; }
    else if (mode == 1) { g_c[b * NH + n] = s; }
    else if (mode == 2) { g_x[b * XD + n] = s; }
    else { s = tanhf(s); g_x[b * XD + n] = s; g_oall[(t * NB + b) * NH + n] = s; }
}

// ---------------- gate reduction + LSTM cell update ------------------------
__global__ void lstm_kernel(int t)
{
    int idx = blockIdx.x * blockDim.x + threadIdx.x;  // 64*512
    int b = idx >> 9, j = idx & 511;
    const float* gy = &g_gatesy[(t * NB + b) * G4];
    float gi = gy[j], gf = gy[NH + j], gg = gy[2 * NH + j], go = gy[3 * NH + j];
    #pragma unroll
    for (int kc = 0; kc < 8; kc++) {
        const float* p = &g_P[(kc * 64 + b) * G4];
        gi += p[j]; gf += p[NH + j]; gg += p[2 * NH + j]; go += p[3 * NH + j];
    }
    float ig = 1.f / (1.f + expf(-gi));
    float fg = 1.f / (1.f + expf(-gf));
    float gt = tanhf(gg);
    float og = 1.f / (1.f + expf(-go));
    float c = fg * g_c[idx] + ig * gt;
    float h = og * tanhf(c);
    g_c[idx] = c;
    g_h[idx] = h;
    g_x[b * XD + NH + j] = h;
    g_u[b * UD + FLOC + j] = h;
}

// ---------------- attention: reduce p, scores, softmax, context ------------
// g_P holds 4 k-split partials of p[b,f] = sum_h h[b,h] * W_attn[h,f]
__global__ void attn_kernel(const float* __restrict__ local)
{
    __shared__ float sp[FLOC];
    __shared__ float se[64];
    int b = blockIdx.x;
    int tid = threadIdx.x;
    for (int f = tid; f < FLOC; f += 256) {
        float s = 0.f;
        #pragma unroll
        for (int kc = 0; kc < 4; kc++)
            s += g_P[(kc * 64 + b) * FLOC + f];
        sp[f] = s;
    }
    __syncthreads();
    int warp = tid >> 5, lane = tid & 31;
    const float* lb = local + b * NR * FLOC;
    for (int r = warp; r < NR; r += 8) {
        const float* lr = lb + r * FLOC;
        float s = 0.f;
        for (int f = lane; f < FLOC; f += 32)
            s = fmaf(lr[f], sp[f], s);
        #pragma unroll
        for (int off = 16; off; off >>= 1)
            s += __shfl_xor_sync(0xffffffffu, s, off);
        if (lane == 0) se[r] = s;
    }
    __syncthreads();
    if (tid < 32) {
        float v0 = (tid < NR) ? se[tid] : -1e30f;
        float v1 = (tid + 32 < NR) ? se[tid + 32] : -1e30f;
        float mx = fmaxf(v0, v1);
        #pragma unroll
        for (int off = 16; off; off >>= 1)
            mx = fmaxf(mx, __shfl_xor_sync(0xffffffffu, mx, off));
        float e0 = (tid < NR) ? expf(v0 - mx) : 0.f;
        float e1 = (tid + 32 < NR) ? expf(v1 - mx) : 0.f;
        float sum = e0 + e1;
        #pragma unroll
        for (int off = 16; off; off >>= 1)
            sum += __shfl_xor_sync(0xffffffffu, sum, off);
        float inv = 1.f / sum;
        if (tid < NR) se[tid] = e0 * inv;
        if (tid + 32 < NR) se[tid + 32] = e1 * inv;
    }
    __syncthreads();
    for (int f = tid; f < FLOC; f += 256) {
        float a = 0.f;
        #pragma unroll 7
        for (int r = 0; r < NR; r++)
            a = fmaf(se[r], lb[r * FLOC + f], a);
        g_u[b * UD + f] = a;  // context vector -> u[:, :1024]
    }
}

// ---------------- big-M tiled GEMM (gatesy precompute + vocab logits) ------
// mode 0: g_gatesy[m*G4+n] = yseq @ W_ihy^T + b1 + b2   (Nw = G4)
// mode 1: out[(b*T+t)*NV+n] = oall  @ W_vocab^T + b1    (m = t*64+b, Nw = NV)
__global__ void mgemm_kernel(int xsel,
                             const float* __restrict__ W, int ldw, int Nw, int K,
                             const float* __restrict__ b1,
                             const float* __restrict__ b2,
                             float* __restrict__ out, int mode)
{
    __shared__ float xs[64 * 65];
    __shared__ float ws[64 * 65];
    const float* X; int ldx;
    if (xsel == 0) { X = g_yseq; ldx = NE; }
    else           { X = g_oall; ldx = NH; }
    int n0 = blockIdx.x << 6;
    int m0 = blockIdx.y << 6;
    int tid = threadIdx.x;
    int tx = tid & 15, ty = tid >> 4;
    float acc[4][4] = {{0.f}};

    for (int kb = 0; kb < K; kb += 64) {
        #pragma unroll
        for (int it = 0; it < 4; it++) {
            int idx = it * 256 + tid;
            int row = idx >> 4;
            int kq = (idx & 15) << 2;
            float4 v = *(const float4*)(X + (m0 + row) * ldx + kb + kq);
            float* d = &xs[row * 65 + kq];
            d[0] = v.x; d[1] = v.y; d[2] = v.z; d[3] = v.w;
            int wr = n0 + row;
            float4 w;
            if (wr < Nw) w = *(const float4*)(W + wr * ldw + kb + kq);
            else         w = make_float4(0.f, 0.f, 0.f, 0.f);
            float* e = &ws[row * 65 + kq];
            e[0] = w.x; e[1] = w.y; e[2] = w.z; e[3] = w.w;
        }
        __syncthreads();
        #pragma unroll 16
        for (int k = 0; k < 64; k++) {
            float xv[4], wv[4];
            #pragma unroll
            for (int i = 0; i < 4; i++) xv[i] = xs[(ty * 4 + i) * 65 + k];
            #pragma unroll
            for (int j = 0; j < 4; j++) wv[j] = ws[(tx + 16 * j) * 65 + k];
            #pragma unroll
            for (int i = 0; i < 4; i++)
                #pragma unroll
                for (int j = 0; j < 4; j++)
                    acc[i][j] = fmaf(xv[i], wv[j], acc[i][j]);
        }
        __syncthreads();
    }
    #pragma unroll
    for (int i = 0; i < 4; i++) {
        int m = m0 + ty * 4 + i;
        #pragma unroll
        for (int j = 0; j < 4; j++) {
            int n = n0 + tx + 16 * j;
            if (n < Nw) {
                float v = acc[i][j] + b1[n];
                if (b2) v += b2[n];
                if (mode == 0) {
                    g_gatesy[m * G4 + n] = v;
                } else {
                    int b = m & 63, t = m >> 6;
                    out[(b * NT + t) * NV + n] = v;
                }
            }
        }
    }
}

// ---------------------------------------------------------------------------
extern "C" void kernel_launch(void* const* d_in, const int* in_sizes, int n_in,
                              void* d_out, int out_size)
{
    const float* local   = (const float*)d_in[0];
    const float* globalf = (const float*)d_in[1];
    const float* q       = (const float*)d_in[2];
    const int*   answers = (const int*)d_in[3];
    const float* emb     = (const float*)d_in[4];
    const float* W_g2o   = (const float*)d_in[5];
    const float* b_g2o   = (const float*)d_in[6];
    const float* W_h     = (const float*)d_in[7];
    const float* W_c     = (const float*)d_in[8];
    const float* W_ih    = (const float*)d_in[9];
    const float* W_hh    = (const float*)d_in[10];
    const float* b_ih    = (const float*)d_in[11];
    const float* b_hh    = (const float*)d_in[12];
    // d_in[13] = W_attn (used in prep)
    const float* W_attn  = (const float*)d_in[13];
    const float* W_u     = (const float*)d_in[14];
    const float* b_u     = (const float*)d_in[15];
    const float* W_vocab = (const float*)d_in[16];
    const float* b_vocab = (const float*)d_in[17];
    float* out = (float*)d_out;

    prep_kernel<<<512, 256>>>(W_ih, W_hh, W_attn, emb, answers);

    // h0 = q @ W_h^T          (K=512, ksplit 4 x chunk 128)
    sg64_kernel<<<8 * 4, 256>>>(q, NQ, 0, W_h, NQ, 0, NH, 128);
    reduce_kernel<<<128, 256>>>(4, NH, nullptr, 0, 0);
    // c0 = q @ W_c^T
    sg64_kernel<<<8 * 4, 256>>>(q, NQ, 0, W_c, NQ, 0, NH, 128);
    reduce_kernel<<<128, 256>>>(4, NH, nullptr, 1, 0);
    // o0 = g @ W_g2o^T + b    (K=2048, ksplit 8 x chunk 256)
    sg64_kernel<<<8 * 8, 256>>>(globalf, 2 * FLOC, 0, W_g2o, 2 * FLOC, 0, NH, 256);
    reduce_kernel<<<128, 256>>>(8, NH, b_g2o, 2, 0);
    // gates_y = yseq @ W_ih[:, :256]^T + b_ih + b_hh
    mgemm_kernel<<<dim3(G4 / 64, (NT * NB) / 64), 256>>>(
        0, W_ih, 768, G4, NE, b_ih, b_hh, nullptr, 0);

    for (int t = 0; t < NT; t++) {
        // gates += [o,h] @ Wrec^T   (N=2048, K=1024, ksplit 8 x 128)
        sg64_kernel<<<32 * 8, 256>>>(nullptr, 0, 1, nullptr, 0, 1, G4, 128);
        lstm_kernel<<<128, 256>>>(t);
        // p = h @ W_attn (as transposed)  (N=1024, K=512, ksplit 4 x 128)
        sg64_kernel<<<16 * 4, 256>>>(nullptr, 0, 2, nullptr, 0, 2, FLOC, 128);
        attn_kernel<<<NB, 256>>>(local);
        // o = tanh([a,h] @ W_u^T + b_u)   (N=512, K=1536, ksplit 12 x 128)
        sg64_kernel<<<8 * 12, 256>>>(nullptr, 0, 3, W_u, UD, 0, NH, 128);
        reduce_kernel<<<128, 256>>>(12, NH, b_u, 3, t);
    }

    // logits = o_all @ W_vocab^T + b_vocab  (M=2048, N=10000, K=512)
    mgemm_kernel<<<dim3((NV + 63) / 64, (NT * NB) / 64), 256>>>(
        1, W_vocab, NH, NV, NH, b_vocab, nullptr, out, 1);
}

// round 3
// speedup vs baseline: 1.0938x; 1.0938x over previous
#include <cuda_runtime.h>
#include <math.h>

#define NB 64
#define NT 32
#define NR 49
#define FLOC 1024
#define NQ 512
#define NE 256
#define NH 512
#define NV 10000
#define G4 2048   // 4*HID
#define XD 1024   // [o(512), h(512)]
#define UD 1536   // [a(1024), h(512)]
#define NBLK 148  // persistent kernel grid (<= SM count, co-resident)

typedef unsigned long long ull;

#define SMEMF (64*65 + 128*65)          // floats of dynamic smem
#define SMEMB (SMEMF * 4)

// ---------------- scratch (device globals; no allocation allowed) ----------
__device__ float g_Wrec[G4 * XD];          // combined [W_ih(:,256:768) | W_hh]
__device__ float g_WattnT[FLOC * NH];      // W_attn transposed [f][h]
__device__ float g_yseq[NT * NB * NE];     // teacher-forced input embeddings
__device__ float g_gatesy[NT * NB * G4];   // y @ W_ihy^T + b_ih + b_hh
__device__ float g_h[NB * NH];
__device__ float g_c[NB * NH];
__device__ float g_x[NB * XD];             // [o, h] GEMM input
__device__ float g_u[NB * UD];             // [a, h] GEMM input
__device__ float g_oall[NT * NB * NH];     // all o_t (vocab GEMM input)
__device__ float g_P[8 * NB * G4];         // k-split partial sums (max shape)
__device__ unsigned int g_barArrive;       // zero-init
__device__ unsigned int g_barGen;          // monotonically increasing across replays

// ---------------- packed f32x2 helpers -------------------------------------
__device__ __forceinline__ ull pack2(float a, float b) {
    ull r; asm("mov.b64 %0, {%1, %2};" : "=l"(r) : "f"(a), "f"(b)); return r;
}
__device__ __forceinline__ float2 unpack2(ull v) {
    float2 r; asm("mov.b64 {%0, %1}, %2;" : "=f"(r.x), "=f"(r.y) : "l"(v)); return r;
}
__device__ __forceinline__ void ffma2(ull& acc, ull a, ull b) {
    asm("fma.rn.f32x2 %0, %1, %2, %0;" : "+l"(acc) : "l"(a), "l"(b));
}

// ---------------- software grid barrier ------------------------------------
__device__ __forceinline__ void gridbar() {
    __threadfence();
    __syncthreads();
    if (threadIdx.x == 0) {
        unsigned int g = *(volatile unsigned int*)&g_barGen;
        if (atomicAdd(&g_barArrive, 1u) == NBLK - 1) {
            g_barArrive = 0;
            __threadfence();
            *(volatile unsigned int*)&g_barGen = g + 1;
        } else {
            while (*(volatile unsigned int*)&g_barGen == g) __nanosleep(20);
        }
    }
    __syncthreads();
}

// ---------------- f32x2 GEMM core: 64(m) x NTILE(n) tile, 64-k blocks ------
// X: [64, ldx] (rows m), W: [Nrows, ldw] (rows n, k contiguous).
// acc[i][jj]: i=0..3 (m = ty*4+i), jj pairs: cols {tx*4+2jj, +1} and group B
// (NTILE=128) at {64+tx*4+2(jj-2), +1}. X read via __ldcg (mutable buffers).
template<int NTILE>
__device__ __forceinline__ void gemm_core(
    const float* __restrict__ X, int ldx,
    const float* __restrict__ W, int ldw,
    int n0, int kbase, int kSteps64, int Nw,
    float* smem, int tid, ull acc[4][4])
{
    float* xs = smem;             // [64][65]
    float* ws = smem + 64 * 65;   // [NTILE][65]
    int tx = tid & 15, ty = tid >> 4;
    for (int kb = 0; kb < kSteps64; kb++) {
        int kpos = kbase + kb * 64;
        #pragma unroll
        for (int it = 0; it < 4; it++) {
            int idx = it * 256 + tid;
            int row = idx >> 4, kq = (idx & 15) << 2;
            float4 v = __ldcg((const float4*)(X + row * ldx + kpos + kq));
            float* d = &xs[row * 65 + kq];
            d[0] = v.x; d[1] = v.y; d[2] = v.z; d[3] = v.w;
        }
        #pragma unroll
        for (int it = 0; it < NTILE / 16; it++) {
            int idx = it * 256 + tid;
            int row = idx >> 4, kq = (idx & 15) << 2;
            int wr = n0 + row;
            float4 v;
            if (wr < Nw) v = *(const float4*)(W + (size_t)wr * ldw + kpos + kq);
            else         v = make_float4(0.f, 0.f, 0.f, 0.f);
            float* d = &ws[row * 65 + kq];
            d[0] = v.x; d[1] = v.y; d[2] = v.z; d[3] = v.w;
        }
        __syncthreads();
        #pragma unroll 8
        for (int k = 0; k < 64; k++) {
            ull xd[4];
            #pragma unroll
            for (int i = 0; i < 4; i++) {
                float x = xs[(ty * 4 + i) * 65 + k];
                xd[i] = pack2(x, x);
            }
            {
                float a0 = ws[(tx * 4 + 0) * 65 + k];
                float a1 = ws[(tx * 4 + 1) * 65 + k];
                float a2 = ws[(tx * 4 + 2) * 65 + k];
                float a3 = ws[(tx * 4 + 3) * 65 + k];
                ull wA0 = pack2(a0, a1), wA1 = pack2(a2, a3);
                #pragma unroll
                for (int i = 0; i < 4; i++) {
                    ffma2(acc[i][0], xd[i], wA0);
                    ffma2(acc[i][1], xd[i], wA1);
                }
            }
            if (NTILE == 128) {
                float b0 = ws[(64 + tx * 4 + 0) * 65 + k];
                float b1 = ws[(64 + tx * 4 + 1) * 65 + k];
                float b2 = ws[(64 + tx * 4 + 2) * 65 + k];
                float b3 = ws[(64 + tx * 4 + 3) * 65 + k];
                ull wB0 = pack2(b0, b1), wB1 = pack2(b2, b3);
                #pragma unroll
                for (int i = 0; i < 4; i++) {
                    ffma2(acc[i][2], xd[i], wB0);
                    ffma2(acc[i][3], xd[i], wB1);
                }
            }
        }
        __syncthreads();
    }
}

// store acc as k-split partials into g_P with row-stride N
template<int NTILE>
__device__ __forceinline__ void store_part(ull acc[4][4], int kc, int n0, int N, int tid)
{
    int tx = tid & 15, ty = tid >> 4;
    #pragma unroll
    for (int i = 0; i < 4; i++) {
        int m = ty * 4 + i;
        float* dst = &g_P[((kc << 6) + m) * N + n0];
        #pragma unroll
        for (int jj = 0; jj < 2; jj++)
            *(float2*)(dst + tx * 4 + jj * 2) = unpack2(acc[i][jj]);
        if (NTILE == 128) {
            #pragma unroll
            for (int jj = 0; jj < 2; jj++)
                *(float2*)(dst + 64 + tx * 4 + jj * 2) = unpack2(acc[i][2 + jj]);
        }
    }
}

// ---------------- one-time prep: weight repack + embedding gather ----------
__global__ void prep_kernel(const float* __restrict__ W_ih,
                            const float* __restrict__ W_hh,
                            const float* __restrict__ W_attn,
                            const float* __restrict__ emb,
                            const int*   __restrict__ answers)
{
    int stride = gridDim.x * blockDim.x;
    int tid0 = blockIdx.x * blockDim.x + threadIdx.x;
    for (int i = tid0; i < G4 * XD; i += stride) {
        int n = i >> 10, k = i & 1023;
        g_Wrec[i] = (k < NH) ? W_ih[n * 768 + 256 + k] : W_hh[n * NH + (k - NH)];
    }
    for (int i = tid0; i < FLOC * NH; i += stride) {
        int f = i >> 9, h = i & 511;
        g_WattnT[i] = W_attn[h * FLOC + f];
    }
    for (int i = tid0; i < NT * NB * NE; i += stride) {
        int m = i >> 8, e = i & 255;
        int t = m >> 6, b = m & 63;
        int tok = (t == 0) ? 1 : answers[b * NT + (t - 1)];
        g_yseq[i] = emb[tok * NE + e];
    }
}

// ---------------- init-only small GEMM (M=64) with k-split partials --------
__global__ void sg64_kernel(const float* __restrict__ X, int ldx,
                            const float* __restrict__ W, int ldw,
                            int N, int kChunk)
{
    __shared__ float xs[64 * 65];
    __shared__ float ws[64 * 65];
    int nTiles = N >> 6;
    int nt = blockIdx.x % nTiles;
    int kc = blockIdx.x / nTiles;
    int n0 = nt << 6;
    int kbase = kc * kChunk;
    int tid = threadIdx.x;
    int tx = tid & 15, ty = tid >> 4;
    float acc[4][4] = {{0.f}};
    for (int kk = 0; kk < kChunk; kk += 64) {
        #pragma unroll
        for (int it = 0; it < 4; it++) {
            int idx = it * 256 + tid;
            int row = idx >> 4, kq = (idx & 15) << 2;
            float4 v = *(const float4*)(X + row * ldx + kbase + kk + kq);
            float* d = &xs[row * 65 + kq];
            d[0] = v.x; d[1] = v.y; d[2] = v.z; d[3] = v.w;
            float4 w = *(const float4*)(W + (n0 + row) * ldw + kbase + kk + kq);
            float* e = &ws[row * 65 + kq];
            e[0] = w.x; e[1] = w.y; e[2] = w.z; e[3] = w.w;
        }
        __syncthreads();
        #pragma unroll 16
        for (int k = 0; k < 64; k++) {
            float xv[4], wv[4];
            #pragma unroll
            for (int i = 0; i < 4; i++) xv[i] = xs[(ty * 4 + i) * 65 + k];
            #pragma unroll
            for (int j = 0; j < 4; j++) wv[j] = ws[(tx + 16 * j) * 65 + k];
            #pragma unroll
            for (int i = 0; i < 4; i++)
                #pragma unroll
                for (int j = 0; j < 4; j++)
                    acc[i][j] = fmaf(xv[i], wv[j], acc[i][j]);
        }
        __syncthreads();
    }
    #pragma unroll
    for (int i = 0; i < 4; i++) {
        int m = ty * 4 + i;
        float* dst = &g_P[(kc * 64 + m) * N + n0];
        #pragma unroll
        for (int j = 0; j < 4; j++)
            dst[tx + 16 * j] = acc[i][j];
    }
}

// init reductions: mode 0: h0 -> g_h + g_x[h]; 1: c0 -> g_c; 2: o0+b -> g_x[o]
__global__ void reduce_kernel(int ksplit, int N, const float* __restrict__ bias, int mode)
{
    int idx = blockIdx.x * blockDim.x + threadIdx.x;
    if (idx >= NB * N) return;
    int b = idx / N, n = idx % N;
    float s = 0.f;
    for (int kc = 0; kc < ksplit; kc++)
        s += g_P[(kc * 64 + b) * N + n];
    if (bias) s += bias[n];
    if (mode == 0)      { g_h[b * NH + n] = s; g_x[b * XD + NH + n] = s; }
    else if (mode == 1) { g_c[b * NH + n] = s; }
    else                { g_x[b * XD + n] = s; }
}

// ---------------- persistent recurrent-loop kernel -------------------------
__global__ void __launch_bounds__(256, 1)
loop_kernel(const float* __restrict__ local,
            const float* __restrict__ W_u,
            const float* __restrict__ b_u)
{
    extern __shared__ float smem[];
    const int bid = blockIdx.x;
    const int tid = threadIdx.x;
    const int BIG = 0x3fffffff;

    // LSTM cell state lives in registers for the 128 lstm-blocks
    float c_reg = 0.f;
    if (bid < 128) c_reg = g_c[bid * 256 + tid];

    for (int t = 0; t < NT; t++) {
        // ---- Stage A: gate partials  P[kc][64][2048] = x @ Wrec^T ---------
        if (bid < 128) {
            int nt = bid & 15, kc = bid >> 4;
            ull acc[4][4] = {{0ULL}};
            gemm_core<128>(g_x, XD, g_Wrec, XD, nt * 128, kc * 128, 2, BIG,
                           smem, tid, acc);
            store_part<128>(acc, kc, nt * 128, G4, tid);
        }
        gridbar();

        // ---- Stage B: LSTM cell (reduce 8 partials + gatesy) --------------
        if (bid < 128) {
            int idx = bid * 256 + tid;         // 64 x 512
            int b = idx >> 9, j = idx & 511;
            const float* gy = &g_gatesy[(t * NB + b) * G4];
            float gi = gy[j], gf = gy[NH + j], gg = gy[2 * NH + j], go = gy[3 * NH + j];
            #pragma unroll
            for (int kc = 0; kc < 8; kc++) {
                const float* p = &g_P[(kc * 64 + b) * G4];
                gi += __ldcg(p + j);
                gf += __ldcg(p + NH + j);
                gg += __ldcg(p + 2 * NH + j);
                go += __ldcg(p + 3 * NH + j);
            }
            float ig = 1.f / (1.f + expf(-gi));
            float fg = 1.f / (1.f + expf(-gf));
            float gt = tanhf(gg);
            float og = 1.f / (1.f + expf(-go));
            c_reg = fg * c_reg + ig * gt;
            float h = og * tanhf(c_reg);
            g_h[idx] = h;
            g_x[b * XD + NH + j] = h;
            g_u[b * UD + FLOC + j] = h;
        }
        gridbar();

        // ---- Stage C: p partials  P[kc][64][1024] = h @ WattnT^T ----------
        if (bid < 128) {
            int nt = bid & 15, kc = bid >> 4;
            ull acc[4][4] = {{0ULL}};
            gemm_core<64>(g_h, NH, g_WattnT, NH, nt * 64, kc * 64, 1, BIG,
                          smem, tid, acc);
            store_part<64>(acc, kc, nt * 64, FLOC, tid);
        }
        gridbar();

        // ---- Stage D: attention (reduce p, scores, softmax, context) ------
        if (bid < NB) {
            float* sp = smem;          // [1024]
            float* se = smem + FLOC;   // [64]
            int b = bid;
            for (int f = tid; f < FLOC; f += 256) {
                float s = 0.f;
                #pragma unroll
                for (int kc = 0; kc < 8; kc++)
                    s += __ldcg(&g_P[(kc * 64 + b) * FLOC + f]);
                sp[f] = s;
            }
            __syncthreads();
            int warp = tid >> 5, lane = tid & 31;
            const float* lb = local + b * NR * FLOC;
            for (int r = warp; r < NR; r += 8) {
                const float* lr = lb + r * FLOC;
                float s = 0.f;
                for (int f = lane * 4; f < FLOC; f += 128) {
                    float4 lv = *(const float4*)(lr + f);
                    float4 pv = *(const float4*)(sp + f);
                    s += lv.x * pv.x + lv.y * pv.y + lv.z * pv.z + lv.w * pv.w;
                }
                #pragma unroll
                for (int off = 16; off; off >>= 1)
                    s += __shfl_xor_sync(0xffffffffu, s, off);
                if (lane == 0) se[r] = s;
            }
            __syncthreads();
            if (tid < 32) {
                float v0 = (tid < NR) ? se[tid] : -1e30f;
                float v1 = (tid + 32 < NR) ? se[tid + 32] : -1e30f;
                float mx = fmaxf(v0, v1);
                #pragma unroll
                for (int off = 16; off; off >>= 1)
                    mx = fmaxf(mx, __shfl_xor_sync(0xffffffffu, mx, off));
                float e0 = (tid < NR) ? expf(v0 - mx) : 0.f;
                float e1 = (tid + 32 < NR) ? expf(v1 - mx) : 0.f;
                float sum = e0 + e1;
                #pragma unroll
                for (int off = 16; off; off >>= 1)
                    sum += __shfl_xor_sync(0xffffffffu, sum, off);
                float inv = 1.f / sum;
                if (tid < NR) se[tid] = e0 * inv;
                if (tid + 32 < NR) se[tid + 32] = e1 * inv;
            }
            __syncthreads();
            {
                int f0 = tid * 4;  // 256*4 = 1024
                float4 a = make_float4(0.f, 0.f, 0.f, 0.f);
                #pragma unroll 7
                for (int r = 0; r < NR; r++) {
                    float w = se[r];
                    float4 lv = *(const float4*)(lb + r * FLOC + f0);
                    a.x = fmaf(w, lv.x, a.x);
                    a.y = fmaf(w, lv.y, a.y);
                    a.z = fmaf(w, lv.z, a.z);
                    a.w = fmaf(w, lv.w, a.w);
                }
                *(float4*)(&g_u[b * UD + f0]) = a;
            }
        }
        gridbar();

        // ---- Stage E: u partials  P[kc][64][512] = u @ W_u^T --------------
        if (bid < 96) {
            int nt = bid & 3, kc = bid >> 2;   // kc 0..23
            ull acc[4][4] = {{0ULL}};
            gemm_core<128>(g_u, UD, W_u, UD, nt * 128, kc * 64, 1, BIG,
                           smem, tid, acc);
            store_part<128>(acc, kc, nt * 128, NH, tid);
        }
        gridbar();

        // ---- Stage F: reduce 24 partials + tanh -> o_t --------------------
        if (bid < 128) {
            int idx = bid * 256 + tid;   // 64 x 512
            int b = idx >> 9, n = idx & 511;
            float s = b_u[n];
            #pragma unroll
            for (int kc = 0; kc < 24; kc++)
                s += __ldcg(&g_P[(kc * 64 + b) * NH + n]);
            s = tanhf(s);
            g_x[b * XD + n] = s;
            g_oall[(t * NB + b) * NH + n] = s;
        }
        gridbar();
    }
}

// ---------------- big GEMM (gatesy precompute / vocab logits) --------------
// mode 0: g_gatesy[m*G4+n] = yseq @ W^T + b1 + b2
// mode 1: out[(b*T+t)*NV+n] = oall @ W^T + b1     (m = t*64+b)
__global__ void __launch_bounds__(256)
mgemm2_kernel(int mode, const float* __restrict__ W, int ldw, int Nw, int K,
              const float* __restrict__ b1, const float* __restrict__ b2,
              float* __restrict__ out)
{
    extern __shared__ float smem[];
    const float* X = (mode == 0) ? g_yseq : g_oall;
    int ldx = (mode == 0) ? NE : NH;
    int n0 = blockIdx.x * 128;
    int m0 = blockIdx.y * 64;
    int tid = threadIdx.x;
    ull acc[4][4] = {{0ULL}};
    gemm_core<128>(X + (size_t)m0 * ldx, ldx, W, ldw, n0, 0, K / 64, Nw,
                   smem, tid, acc);
    int tx = tid & 15, ty = tid >> 4;
    #pragma unroll
    for (int i = 0; i < 4; i++) {
        int m = m0 + ty * 4 + i;
        #pragma unroll
        for (int g = 0; g < 2; g++) {
            #pragma unroll
            for (int jj = 0; jj < 2; jj++) {
                int n = n0 + g * 64 + tx * 4 + jj * 2;
                float2 v = unpack2(acc[i][g * 2 + jj]);
                #pragma unroll
                for (int e = 0; e < 2; e++) {
                    int nn = n + e;
                    if (nn >= Nw) continue;
                    float val = (e == 0 ? v.x : v.y) + b1[nn];
                    if (b2) val += b2[nn];
                    if (mode == 0) {
                        g_gatesy[m * G4 + nn] = val;
                    } else {
                        int b = m & 63, t = m >> 6;
                        out[((size_t)b * NT + t) * NV + nn] = val;
                    }
                }
            }
        }
    }
}

// ---------------------------------------------------------------------------
extern "C" void kernel_launch(void* const* d_in, const int* in_sizes, int n_in,
                              void* d_out, int out_size)
{
    const float* local   = (const float*)d_in[0];
    const float* globalf = (const float*)d_in[1];
    const float* q       = (const float*)d_in[2];
    const int*   answers = (const int*)d_in[3];
    const float* emb     = (const float*)d_in[4];
    const float* W_g2o   = (const float*)d_in[5];
    const float* b_g2o   = (const float*)d_in[6];
    const float* W_h     = (const float*)d_in[7];
    const float* W_c     = (const float*)d_in[8];
    const float* W_ih    = (const float*)d_in[9];
    const float* W_hh    = (const float*)d_in[10];
    const float* b_ih    = (const float*)d_in[11];
    const float* b_hh    = (const float*)d_in[12];
    const float* W_attn  = (const float*)d_in[13];
    const float* W_u     = (const float*)d_in[14];
    const float* b_u     = (const float*)d_in[15];
    const float* W_vocab = (const float*)d_in[16];
    const float* b_vocab = (const float*)d_in[17];
    float* out = (float*)d_out;

    cudaFuncSetAttribute(loop_kernel,   cudaFuncAttributeMaxDynamicSharedMemorySize, SMEMB);
    cudaFuncSetAttribute(mgemm2_kernel, cudaFuncAttributeMaxDynamicSharedMemorySize, SMEMB);

    prep_kernel<<<512, 256>>>(W_ih, W_hh, W_attn, emb, answers);

    // h0 = q @ W_h^T
    sg64_kernel<<<8 * 4, 256>>>(q, NQ, W_h, NQ, NH, 128);
    reduce_kernel<<<128, 256>>>(4, NH, nullptr, 0);
    // c0 = q @ W_c^T
    sg64_kernel<<<8 * 4, 256>>>(q, NQ, W_c, NQ, NH, 128);
    reduce_kernel<<<128, 256>>>(4, NH, nullptr, 1);
    // o0 = g @ W_g2o^T + b
    sg64_kernel<<<8 * 8, 256>>>(globalf, 2 * FLOC, W_g2o, 2 * FLOC, NH, 256);
    reduce_kernel<<<128, 256>>>(8, NH, b_g2o, 2);

    // gates_y = yseq @ W_ih[:, :256]^T + b_ih + b_hh
    mgemm2_kernel<<<dim3(G4 / 128, (NT * NB) / 64), 256, SMEMB>>>(
        0, W_ih, 768, G4, NE, b_ih, b_hh, nullptr);

    // the entire 32-step recurrence in one persistent kernel
    loop_kernel<<<NBLK, 256, SMEMB>>>(local, W_u, b_u);

    // logits = o_all @ W_vocab^T + b_vocab
    mgemm2_kernel<<<dim3((NV + 127) / 128, (NT * NB) / 64), 256, SMEMB>>>(
        1, W_vocab, NH, NV, NH, b_vocab, nullptr, out);
}